// round 2
// baseline (speedup 1.0000x reference)
#include <cuda_runtime.h>
#include <math.h>

#define BQ 2
#define LQ 4
#define NP 1024
#define DIMF 512
#define NHEADS 8
#define DHD 64
#define INNER 512
#define NS 8
#define LK 32
#define RAD2 0.04f
#define ROWS (BQ*LQ*NP)   // 8192

// ---------------- scratch (static device allocations) ----------------
__device__ float g_normf[(size_t)ROWS*DIMF];          // 16.8 MB
__device__ float g_qkv[(size_t)ROWS*3*INNER];         // 50.3 MB
__device__ float g_attnout[(size_t)ROWS*INNER];       // 16.8 MB
__device__ int   g_idx[(size_t)LQ*BQ*LQ*NP*NS];       // 1 MB

// ---------------- LayerNorm ----------------
__global__ void ln_kernel(const float* __restrict__ f,
                          const float* __restrict__ gamma,
                          const float* __restrict__ beta) {
    int row = blockIdx.x;
    int t = threadIdx.x;                    // 128 threads
    const float* x = f + (size_t)row*DIMF;
    float v[4]; float s=0.f, ss=0.f;
#pragma unroll
    for (int i=0;i<4;i++){ v[i]=x[t+128*i]; s+=v[i]; ss+=v[i]*v[i]; }
#pragma unroll
    for (int o=16;o>0;o>>=1){ s+=__shfl_down_sync(0xffffffffu,s,o); ss+=__shfl_down_sync(0xffffffffu,ss,o); }
    __shared__ float rs[4], rss[4];
    if ((t&31)==0){ rs[t>>5]=s; rss[t>>5]=ss; }
    __syncthreads();
    s  = rs[0]+rs[1]+rs[2]+rs[3];
    ss = rss[0]+rss[1]+rss[2]+rss[3];
    float mu  = s*(1.f/DIMF);
    float var = ss*(1.f/DIMF) - mu*mu;
    float rstd = rsqrtf(var + 1e-5f);
    float* o = g_normf + (size_t)row*DIMF;
#pragma unroll
    for (int i=0;i<4;i++){ int c=t+128*i; o[c] = (v[i]-mu)*rstd*gamma[c]+beta[c]; }
}

// ---------------- SGEMM 128x128x8, 256 threads, 8x8 per thread ----------------
// C[M,Nn] = A[M,512] @ B[512,Nn]; EPI: C = gelu(C + bias) + resid
template<bool EPI>
__global__ void sgemm_kernel(const float* __restrict__ A,
                             const float* __restrict__ Bm,
                             float* __restrict__ C, int Nn,
                             const float* __restrict__ bias,
                             const float* __restrict__ resid) {
    __shared__ float As[8][128];
    __shared__ float Bs[8][128];
    int tid = threadIdx.x;
    int bx = blockIdx.x, by = blockIdx.y;
    int arow = tid>>1,  acol=(tid&1)*4;
    int brow = tid>>5,  bcol=(tid&31)*4;
    int tx = (tid&15)*8, ty=(tid>>4)*8;
    const float* Ap = A  + (size_t)(by*128)*512;
    const float* Bp = Bm + bx*128;
    float acc[8][8];
#pragma unroll
    for (int m=0;m<8;m++)
#pragma unroll
      for (int n=0;n<8;n++) acc[m][n]=0.f;

    for (int k0=0;k0<512;k0+=8){
        float4 a4 = *(const float4*)(Ap + (size_t)arow*512 + k0 + acol);
        As[acol+0][arow]=a4.x; As[acol+1][arow]=a4.y;
        As[acol+2][arow]=a4.z; As[acol+3][arow]=a4.w;
        float4 b4 = *(const float4*)(Bp + (size_t)(k0+brow)*Nn + bcol);
        *(float4*)&Bs[brow][bcol] = b4;
        __syncthreads();
#pragma unroll
        for (int k=0;k<8;k++){
            float ar[8], br[8];
#pragma unroll
            for (int m=0;m<8;m++) ar[m]=As[k][ty+m];
#pragma unroll
            for (int n=0;n<8;n++) br[n]=Bs[k][tx+n];
#pragma unroll
            for (int m=0;m<8;m++)
#pragma unroll
              for (int n=0;n<8;n++) acc[m][n] = fmaf(ar[m], br[n], acc[m][n]);
        }
        __syncthreads();
    }
#pragma unroll
    for (int m=0;m<8;m++){
        int row = by*128+ty+m;
#pragma unroll
        for (int n=0;n<8;n++){
            int col = bx*128+tx+n;
            float x = acc[m][n];
            if (EPI){
                x += bias[col];
                x  = 0.5f*x*(1.0f+erff(x*0.70710678118654752440f));
                x += resid[(size_t)row*Nn + col];
            }
            C[(size_t)row*Nn + col] = x;
        }
    }
}

// ---------------- Ball query: one warp per (frame_i, batch, frame_j, point) ----------------
__global__ void ballq_kernel(const float* __restrict__ xyz){
    int gw   = (blockIdx.x*blockDim.x + threadIdx.x)>>5;   // 0..32767
    int lane = threadIdx.x & 31;
    int p  =  gw & (NP-1);
    int j  = (gw>>10)&3;
    int bb = (gw>>12)&1;
    int i  =  gw>>13;
    const float* qp = xyz + (size_t)((bb*LQ+i)*NP + p)*3;
    float qx=qp[0], qy=qp[1], qz=qp[2];
    const float* ref = xyz + (size_t)((bb*LQ+j)*NP)*3;
    int cnt=0; int out[NS];
    for (int c=0;c<NP;c+=32){
        const float* rp = ref + (c+lane)*3;
        float dx=rp[0]-qx, dy=rp[1]-qy, dz=rp[2]-qz;
        unsigned mask = __ballot_sync(0xffffffffu, dx*dx+dy*dy+dz*dz < RAD2);
        while (mask && cnt<NS){ int bp=__ffs(mask)-1; out[cnt++]=c+bp; mask&=mask-1; }
        if (cnt>=NS) break;
    }
    int fill = (cnt>0)?out[0]:0;
    for (int s=cnt;s<NS;s++) out[s]=fill;
    if (lane<NS) g_idx[(size_t)gw*NS + lane] = out[lane];
}

// ---------------- Fused attention: one block per query point, one warp per head ----------------
__global__ void attn_kernel(const float* __restrict__ xyz,
                            const float* __restrict__ ws){
    __shared__ int   srow[LK];
    __shared__ float sdisp[LK][3];
    __shared__ float sq[INNER];
    __shared__ float sattn[NHEADS][LK];
    int tid = threadIdx.x;                  // 256
    int p  =  blockIdx.x & (NP-1);
    int bb = (blockIdx.x>>10)&1;
    int i  =  blockIdx.x>>11;
    int rowq = (bb*LQ+i)*NP+p;
    const float* qrow = g_qkv + (size_t)rowq*1536;
    float2 q2 = *(const float2*)(qrow + tid*2);
    sq[tid*2]=q2.x; sq[tid*2+1]=q2.y;
    if (tid<LK){
        int j = tid>>3, s = tid&7;
        int gi   = g_idx[((size_t)((i*BQ+bb)*LQ + j)*NP + p)*NS + s];
        int rowk = (bb*LQ+j)*NP + gi;
        srow[tid]=rowk;
        sdisp[tid][0] = xyz[(size_t)rowk*3+0]-xyz[(size_t)rowq*3+0];
        sdisp[tid][1] = xyz[(size_t)rowk*3+1]-xyz[(size_t)rowq*3+1];
        sdisp[tid][2] = xyz[(size_t)rowk*3+2]-xyz[(size_t)rowq*3+2];
    }
    __syncthreads();
    int h = tid>>5, lane = tid&31;
    // --- logits: lane = key j ---
    const float* kp = g_qkv + (size_t)srow[lane]*1536 + 512 + h*64;
    float lg = 0.f;
#pragma unroll
    for (int d=0;d<64;d+=4){
        float4 kk = *(const float4*)(kp+d);
        lg = fmaf(kk.x, sq[h*64+d],   lg);
        lg = fmaf(kk.y, sq[h*64+d+1], lg);
        lg = fmaf(kk.z, sq[h*64+d+2], lg);
        lg = fmaf(kk.w, sq[h*64+d+3], lg);
    }
    lg *= 0.125f;
    // --- softmax across warp ---
    float mx = lg;
#pragma unroll
    for (int o=16;o>0;o>>=1) mx = fmaxf(mx, __shfl_xor_sync(0xffffffffu,mx,o));
    float e = expf(lg-mx);
    float sm = e;
#pragma unroll
    for (int o=16;o>0;o>>=1) sm += __shfl_xor_sync(0xffffffffu,sm,o);
    float a = e/sm;
    sattn[h][lane]=a;
    // --- spatial max term: max_j attn_j * disp_j[c] ---
    float m0 = a*sdisp[lane][0], m1 = a*sdisp[lane][1], m2 = a*sdisp[lane][2];
#pragma unroll
    for (int o=16;o>0;o>>=1){
        m0 = fmaxf(m0, __shfl_xor_sync(0xffffffffu,m0,o));
        m1 = fmaxf(m1, __shfl_xor_sync(0xffffffffu,m1,o));
        m2 = fmaxf(m2, __shfl_xor_sync(0xffffffffu,m2,o));
    }
    __syncwarp();
    // --- attn @ V: lane = output dim pair (coalesced per key row) ---
    float acc0=0.f, acc1=0.f;
#pragma unroll 4
    for (int jj=0;jj<LK;jj++){
        float aw = sattn[h][jj];
        const float* vp = g_qkv + (size_t)srow[jj]*1536 + 1024 + h*64 + lane*2;
        float2 vv = *(const float2*)vp;
        acc0 = fmaf(aw, vv.x, acc0);
        acc1 = fmaf(aw, vv.y, acc1);
    }
    int d0 = lane*2;
    float sp0 = m0*ws[d0]   + m1*ws[64+d0]   + m2*ws[128+d0];
    float sp1 = m0*ws[d0+1] + m1*ws[64+d0+1] + m2*ws[128+d0+1];
    float* op = g_attnout + (size_t)rowq*INNER + h*64 + d0;
    op[0]=acc0+sp0; op[1]=acc1+sp1;
}

// ---------------- launch ----------------
extern "C" void kernel_launch(void* const* d_in, const int* in_sizes, int n_in,
                              void* d_out, int out_size){
    const float* xyz       = (const float*)d_in[0];
    const float* feature   = (const float*)d_in[1];
    const float* gamma     = (const float*)d_in[2];
    const float* beta      = (const float*)d_in[3];
    const float* w_qkv     = (const float*)d_in[4];
    const float* w_spatial = (const float*)d_in[5];
    const float* w_out     = (const float*)d_in[6];
    const float* b_out     = (const float*)d_in[7];
    float* out = (float*)d_out;

    void *p_normf=nullptr, *p_qkv=nullptr, *p_attnout=nullptr;
    cudaGetSymbolAddress(&p_normf,   g_normf);
    cudaGetSymbolAddress(&p_qkv,     g_qkv);
    cudaGetSymbolAddress(&p_attnout, g_attnout);

    ln_kernel<<<ROWS,128>>>(feature,gamma,beta);

    dim3 g1(1536/128, ROWS/128);
    sgemm_kernel<false><<<g1,256>>>((const float*)p_normf, w_qkv,
                                    (float*)p_qkv, 1536, nullptr, nullptr);

    ballq_kernel<<<(LQ*BQ*LQ*NP*32)/256, 256>>>(xyz);

    attn_kernel<<<LQ*BQ*NP, 256>>>(xyz, w_spatial);

    dim3 g2(512/128, ROWS/128);
    sgemm_kernel<true><<<g2,256>>>((const float*)p_attnout, w_out,
                                   out, 512, b_out, feature);
}

// round 4
// speedup vs baseline: 1.4700x; 1.4700x over previous
#include <cuda_runtime.h>
#include <math.h>
#include <stdint.h>

#define BQ 2
#define LQ 4
#define NP 1024
#define DIMF 512
#define NHEADS 8
#define DHD 64
#define INNER 512
#define NS 8
#define LK 32
#define RAD2 0.04f
#define ROWS (BQ*LQ*NP)   // 8192

// ---------------- scratch (static device allocations) ----------------
__device__ float g_normf[(size_t)ROWS*DIMF];
__device__ float g_qkv[(size_t)ROWS*3*INNER];
__device__ float g_attnout[(size_t)ROWS*INNER];
__device__ int   g_idx[(size_t)LQ*BQ*LQ*NP*NS];

__device__ __forceinline__ unsigned f2tf32(float x){
    unsigned r; asm("cvt.rna.tf32.f32 %0, %1;" : "=r"(r) : "f"(x)); return r;
}

// ---------------- LayerNorm ----------------
__global__ void ln_kernel(const float* __restrict__ f,
                          const float* __restrict__ gamma,
                          const float* __restrict__ beta) {
    int row = blockIdx.x;
    int t = threadIdx.x;                    // 128 threads
    const float* x = f + (size_t)row*DIMF;
    float v[4]; float s=0.f, ss=0.f;
#pragma unroll
    for (int i=0;i<4;i++){ v[i]=x[t+128*i]; s+=v[i]; ss+=v[i]*v[i]; }
#pragma unroll
    for (int o=16;o>0;o>>=1){ s+=__shfl_down_sync(0xffffffffu,s,o); ss+=__shfl_down_sync(0xffffffffu,ss,o); }
    __shared__ float rs[4], rss[4];
    if ((t&31)==0){ rs[t>>5]=s; rss[t>>5]=ss; }
    __syncthreads();
    s  = rs[0]+rs[1]+rs[2]+rs[3];
    ss = rss[0]+rss[1]+rss[2]+rss[3];
    float mu  = s*(1.f/DIMF);
    float var = ss*(1.f/DIMF) - mu*mu;
    float rstd = rsqrtf(var + 1e-5f);
    float* o = g_normf + (size_t)row*DIMF;
#pragma unroll
    for (int i=0;i<4;i++){ int c=t+128*i; o[c] = (v[i]-mu)*rstd*gamma[c]+beta[c]; }
}

// ---------------- TF32 tensor-core GEMM: 128x128 tile, K-chunk 32 ----------------
// C[M,Nn] = A[M,512] @ B[512,Nn]; EPI: C = gelu(C+bias)+resid
#define SA_STRIDE 36   // banks (4g+t) unique -> conflict free
#define SB_STRIDE 136  // banks (8t+g) unique -> conflict free
template<bool EPI>
__global__ __launch_bounds__(256,2)
void mma_gemm(const float* __restrict__ A,
              const float* __restrict__ Bm,
              float* __restrict__ C, int Nn,
              const float* __restrict__ bias,
              const float* __restrict__ resid)
{
    __shared__ unsigned sA[128*SA_STRIDE];
    __shared__ unsigned sB[32*SB_STRIDE];
    int tid = threadIdx.x;
    int bx = blockIdx.x, by = blockIdx.y;
    int w = tid>>5, lane = tid&31;
    int wm = w>>2, wn = w&3;               // 2x4 warp grid, each warp 64x32
    int g = lane>>2, t4 = lane&3;

    float acc[4][4][4];
#pragma unroll
    for (int a=0;a<4;a++)
#pragma unroll
      for (int b=0;b<4;b++)
#pragma unroll
        for (int c=0;c<4;c++) acc[a][b][c]=0.f;

    for (int k0=0;k0<512;k0+=32){
        // stage A 128x32
#pragma unroll
        for (int p=0;p<4;p++){
            int r  = (p*256+tid)>>3;
            int c4 = (tid&7)*4;
            float4 v = *(const float4*)(A + (size_t)(by*128+r)*512 + k0 + c4);
            unsigned* d = &sA[r*SA_STRIDE + c4];
            d[0]=f2tf32(v.x); d[1]=f2tf32(v.y); d[2]=f2tf32(v.z); d[3]=f2tf32(v.w);
        }
        // stage B 32x128
#pragma unroll
        for (int p=0;p<4;p++){
            int r  = p*8 + (tid>>5);
            int c4 = (tid&31)*4;
            float4 v = *(const float4*)(Bm + (size_t)(k0+r)*Nn + bx*128 + c4);
            unsigned* d = &sB[r*SB_STRIDE + c4];
            d[0]=f2tf32(v.x); d[1]=f2tf32(v.y); d[2]=f2tf32(v.z); d[3]=f2tf32(v.w);
        }
        __syncthreads();
#pragma unroll
        for (int ks=0;ks<4;ks++){
            int k8 = ks*8;
            unsigned af[4][4], bf[4][2];
#pragma unroll
            for (int mi=0;mi<4;mi++){
                int rb = wm*64 + mi*16;
                af[mi][0]=sA[(rb+g  )*SA_STRIDE + k8+t4  ];
                af[mi][1]=sA[(rb+g+8)*SA_STRIDE + k8+t4  ];
                af[mi][2]=sA[(rb+g  )*SA_STRIDE + k8+t4+4];
                af[mi][3]=sA[(rb+g+8)*SA_STRIDE + k8+t4+4];
            }
#pragma unroll
            for (int ni=0;ni<4;ni++){
                int cb = wn*32 + ni*8;
                bf[ni][0]=sB[(k8+t4  )*SB_STRIDE + cb+g];
                bf[ni][1]=sB[(k8+t4+4)*SB_STRIDE + cb+g];
            }
#pragma unroll
            for (int mi=0;mi<4;mi++)
#pragma unroll
              for (int ni=0;ni<4;ni++){
                asm volatile(
                  "mma.sync.aligned.m16n8k8.row.col.f32.tf32.tf32.f32 "
                  "{%0,%1,%2,%3}, {%4,%5,%6,%7}, {%8,%9}, {%0,%1,%2,%3};"
                  : "+f"(acc[mi][ni][0]), "+f"(acc[mi][ni][1]),
                    "+f"(acc[mi][ni][2]), "+f"(acc[mi][ni][3])
                  : "r"(af[mi][0]), "r"(af[mi][1]), "r"(af[mi][2]), "r"(af[mi][3]),
                    "r"(bf[ni][0]), "r"(bf[ni][1]));
              }
        }
        __syncthreads();
    }
    // epilogue
#pragma unroll
    for (int mi=0;mi<4;mi++){
        int r0 = by*128 + wm*64 + mi*16 + g;
#pragma unroll
        for (int ni=0;ni<4;ni++){
            int c0 = bx*128 + wn*32 + ni*8 + 2*t4;
#pragma unroll
            for (int half=0; half<2; half++){
                int r = r0 + half*8;
                float x0 = acc[mi][ni][half*2+0];
                float x1 = acc[mi][ni][half*2+1];
                if (EPI){
                    x0 += bias[c0];  x1 += bias[c0+1];
                    x0  = 0.5f*x0*(1.0f+erff(x0*0.70710678118654752440f));
                    x1  = 0.5f*x1*(1.0f+erff(x1*0.70710678118654752440f));
                    x0 += resid[(size_t)r*Nn + c0];
                    x1 += resid[(size_t)r*Nn + c0+1];
                }
                float2 v2 = make_float2(x0,x1);
                *(float2*)&C[(size_t)r*Nn + c0] = v2;
            }
        }
    }
}

// ---------------- Ball query ----------------
__global__ void ballq_kernel(const float* __restrict__ xyz){
    int gw   = (blockIdx.x*blockDim.x + threadIdx.x)>>5;
    int lane = threadIdx.x & 31;
    int p  =  gw & (NP-1);
    int j  = (gw>>10)&3;
    int bb = (gw>>12)&1;
    int i  =  gw>>13;
    const float* qp = xyz + (size_t)((bb*LQ+i)*NP + p)*3;
    float qx=qp[0], qy=qp[1], qz=qp[2];
    const float* ref = xyz + (size_t)((bb*LQ+j)*NP)*3;
    int cnt=0; int out[NS];
    for (int c=0;c<NP;c+=32){
        const float* rp = ref + (c+lane)*3;
        float dx=rp[0]-qx, dy=rp[1]-qy, dz=rp[2]-qz;
        unsigned mask = __ballot_sync(0xffffffffu, dx*dx+dy*dy+dz*dz < RAD2);
        while (mask && cnt<NS){ int bp=__ffs(mask)-1; out[cnt++]=c+bp; mask&=mask-1; }
        if (cnt>=NS) break;
    }
    int fill = (cnt>0)?out[0]:0;
    for (int s=cnt;s<NS;s++) out[s]=fill;
    if (lane<NS) g_idx[(size_t)gw*NS + lane] = out[lane];
}

// ---------------- Fused attention with smem-staged K ----------------
#define SK_STRIDE 516   // LDS.128: lanes 0-7 cover all 8 bank-quads -> conflict free
__global__ void attn_kernel(const float* __restrict__ xyz,
                            const float* __restrict__ ws){
    extern __shared__ float smem[];
    float* sK    = smem;                    // 32*516
    float* sq    = sK + 32*SK_STRIDE;       // 512
    float* sattn = sq + 512;                // 8*32
    float* sdisp = sattn + 256;             // 32*3
    int*   srow  = (int*)(sdisp + 96);      // 32

    int tid = threadIdx.x;                  // 256
    int p  =  blockIdx.x & (NP-1);
    int bb = (blockIdx.x>>10)&1;
    int i  =  blockIdx.x>>11;
    int rowq = (bb*LQ+i)*NP+p;
    const float* qrow = g_qkv + (size_t)rowq*1536;
    float2 q2 = *(const float2*)(qrow + tid*2);
    sq[tid*2]=q2.x; sq[tid*2+1]=q2.y;
    if (tid<LK){
        int j = tid>>3, s = tid&7;
        int gi   = g_idx[((size_t)((i*BQ+bb)*LQ + j)*NP + p)*NS + s];
        int rowk = (bb*LQ+j)*NP + gi;
        srow[tid]=rowk;
        sdisp[tid*3+0] = xyz[(size_t)rowk*3+0]-xyz[(size_t)rowq*3+0];
        sdisp[tid*3+1] = xyz[(size_t)rowk*3+1]-xyz[(size_t)rowq*3+1];
        sdisp[tid*3+2] = xyz[(size_t)rowk*3+2]-xyz[(size_t)rowq*3+2];
    }
    __syncthreads();
    // stage K rows coalesced: 32 rows x 512 floats
#pragma unroll
    for (int pp=0;pp<16;pp++){
        int idx = pp*256 + tid;
        int r  = idx>>7;
        int c4 = (idx&127)*4;
        float4 v = *(const float4*)(g_qkv + (size_t)srow[r]*1536 + 512 + c4);
        *(float4*)&sK[r*SK_STRIDE + c4] = v;
    }
    __syncthreads();

    int h = tid>>5, lane = tid&31;
    // --- logits from smem: lane = key j ---
    const float* kp = &sK[lane*SK_STRIDE + h*64];
    const float* qh = &sq[h*64];
    float lg = 0.f;
#pragma unroll
    for (int d=0;d<64;d+=4){
        float4 kk = *(const float4*)(kp+d);
        lg = fmaf(kk.x, qh[d],   lg);
        lg = fmaf(kk.y, qh[d+1], lg);
        lg = fmaf(kk.z, qh[d+2], lg);
        lg = fmaf(kk.w, qh[d+3], lg);
    }
    lg *= 0.125f;
    // --- softmax across warp ---
    float mx = lg;
#pragma unroll
    for (int o=16;o>0;o>>=1) mx = fmaxf(mx, __shfl_xor_sync(0xffffffffu,mx,o));
    float e = expf(lg-mx);
    float sm = e;
#pragma unroll
    for (int o=16;o>0;o>>=1) sm += __shfl_xor_sync(0xffffffffu,sm,o);
    float a = e/sm;
    sattn[h*32+lane]=a;
    // --- spatial max term ---
    float m0 = a*sdisp[lane*3+0], m1 = a*sdisp[lane*3+1], m2 = a*sdisp[lane*3+2];
#pragma unroll
    for (int o=16;o>0;o>>=1){
        m0 = fmaxf(m0, __shfl_xor_sync(0xffffffffu,m0,o));
        m1 = fmaxf(m1, __shfl_xor_sync(0xffffffffu,m1,o));
        m2 = fmaxf(m2, __shfl_xor_sync(0xffffffffu,m2,o));
    }
    __syncwarp();
    // --- attn @ V (coalesced from global) ---
    float acc0=0.f, acc1=0.f;
#pragma unroll 4
    for (int jj=0;jj<LK;jj++){
        float aw = sattn[h*32+jj];
        const float* vp = g_qkv + (size_t)srow[jj]*1536 + 1024 + h*64 + lane*2;
        float2 vv = *(const float2*)vp;
        acc0 = fmaf(aw, vv.x, acc0);
        acc1 = fmaf(aw, vv.y, acc1);
    }
    int d0 = lane*2;
    float sp0 = m0*ws[d0]   + m1*ws[64+d0]   + m2*ws[128+d0];
    float sp1 = m0*ws[d0+1] + m1*ws[64+d0+1] + m2*ws[128+d0+1];
    float* op = g_attnout + (size_t)rowq*INNER + h*64 + d0;
    op[0]=acc0+sp0; op[1]=acc1+sp1;
}

#define ATTN_SMEM ((32*SK_STRIDE + 512 + 256 + 96 + 32)*4)

// ---------------- launch ----------------
extern "C" void kernel_launch(void* const* d_in, const int* in_sizes, int n_in,
                              void* d_out, int out_size){
    const float* xyz       = (const float*)d_in[0];
    const float* feature   = (const float*)d_in[1];
    const float* gamma     = (const float*)d_in[2];
    const float* beta      = (const float*)d_in[3];
    const float* w_qkv     = (const float*)d_in[4];
    const float* w_spatial = (const float*)d_in[5];
    const float* w_out     = (const float*)d_in[6];
    const float* b_out     = (const float*)d_in[7];
    float* out = (float*)d_out;

    void *p_normf=nullptr, *p_qkv=nullptr, *p_attnout=nullptr;
    cudaGetSymbolAddress(&p_normf,   g_normf);
    cudaGetSymbolAddress(&p_qkv,     g_qkv);
    cudaGetSymbolAddress(&p_attnout, g_attnout);

    cudaFuncSetAttribute(attn_kernel,
        cudaFuncAttributeMaxDynamicSharedMemorySize, ATTN_SMEM);

    ln_kernel<<<ROWS,128>>>(feature,gamma,beta);

    dim3 g1(1536/128, ROWS/128);
    mma_gemm<false><<<g1,256>>>((const float*)p_normf, w_qkv,
                                (float*)p_qkv, 1536, nullptr, nullptr);

    ballq_kernel<<<(LQ*BQ*LQ*NP*32)/256, 256>>>(xyz);

    attn_kernel<<<LQ*BQ*NP, 256, ATTN_SMEM>>>(xyz, w_spatial);

    dim3 g2(512/128, ROWS/128);
    mma_gemm<true><<<g2,256>>>((const float*)p_attnout, w_out,
                               out, 512, b_out, feature);
}

// round 7
// speedup vs baseline: 2.8375x; 1.9302x over previous
#include <cuda_runtime.h>
#include <math.h>
#include <stdint.h>

#define BQ 2
#define LQ 4
#define NP 1024
#define DIMF 512
#define NHEADS 8
#define DHD 64
#define INNER 512
#define NS 8
#define LK 32
#define RAD2 0.04f
#define ROWS (BQ*LQ*NP)   // 8192

__device__ float g_normf[(size_t)ROWS*DIMF];
__device__ float g_qkv[(size_t)ROWS*3*INNER];
__device__ float g_attnout[(size_t)ROWS*INNER];
__device__ int   g_idx[(size_t)LQ*BQ*LQ*NP*NS];

#define CP_ASYNC16(dst,src) asm volatile("cp.async.cg.shared.global [%0],[%1],16;\n"::"r"(dst),"l"(src))
#define CP_COMMIT           asm volatile("cp.async.commit_group;\n")
#define CP_WAIT(n)          asm volatile("cp.async.wait_group %0;\n"::"n"(n))

// ---------------- LayerNorm ----------------
__global__ void ln_kernel(const float* __restrict__ f,
                          const float* __restrict__ gamma,
                          const float* __restrict__ beta) {
    int row = blockIdx.x;
    int t = threadIdx.x;                    // 128 threads
    const float* x = f + (size_t)row*DIMF;
    float v[4]; float s=0.f, ss=0.f;
#pragma unroll
    for (int i=0;i<4;i++){ v[i]=x[t+128*i]; s+=v[i]; ss+=v[i]*v[i]; }
#pragma unroll
    for (int o=16;o>0;o>>=1){ s+=__shfl_down_sync(0xffffffffu,s,o); ss+=__shfl_down_sync(0xffffffffu,ss,o); }
    __shared__ float rs[4], rss[4];
    if ((t&31)==0){ rs[t>>5]=s; rss[t>>5]=ss; }
    __syncthreads();
    s  = rs[0]+rs[1]+rs[2]+rs[3];
    ss = rss[0]+rss[1]+rss[2]+rss[3];
    float mu  = s*(1.f/DIMF);
    float var = ss*(1.f/DIMF) - mu*mu;
    float rstd = rsqrtf(var + 1e-5f);
    float* o = g_normf + (size_t)row*DIMF;
#pragma unroll
    for (int i=0;i<4;i++){ int c=t+128*i; o[c] = (v[i]-mu)*rstd*gamma[c]+beta[c]; }
}

// ---------------- TF32 tensor-core GEMM, cp.async double-buffered ----------------
#define SA_STRIDE 36
#define SB_STRIDE 136
#define SA_BUF (128*SA_STRIDE)
#define SB_BUF (32*SB_STRIDE)
#define GEMM_SMEM ((2*SA_BUF + 2*SB_BUF)*4)

template<bool EPI>
__global__ __launch_bounds__(256,2)
void mma_gemm(const float* __restrict__ A,
              const float* __restrict__ Bm,
              float* __restrict__ C, int Nn,
              const float* __restrict__ bias,
              const float* __restrict__ resid)
{
    extern __shared__ unsigned smemu[];
    unsigned* sA = smemu;               // 2 x 128x36
    unsigned* sB = smemu + 2*SA_BUF;    // 2 x 32x136
    int tid = threadIdx.x;
    int bx = blockIdx.x, by = blockIdx.y;
    int w = tid>>5, lane = tid&31;
    int wm = w>>2, wn = w&3;
    int g = lane>>2, t4 = lane&3;

    // per-thread staging coords
    int ar  = tid>>3,        ac4 = (tid&7)*4;    // covers 32 rows per pass (4 passes)
    int br  = tid>>5,        bc4 = (tid&31)*4;   // covers 8 rows per pass (4 passes)
    const float* Abase = A  + (size_t)(by*128)*512;
    const float* Bbase = Bm + bx*128;

    float acc[4][4][4];
#pragma unroll
    for (int a=0;a<4;a++)
#pragma unroll
      for (int b=0;b<4;b++)
#pragma unroll
        for (int c=0;c<4;c++) acc[a][b][c]=0.f;

    // issue cp.async for k-chunk k0 into buffer buf
    auto issue = [&](int k0, int buf){
        unsigned* dA = sA + buf*SA_BUF;
        unsigned* dB = sB + buf*SB_BUF;
#pragma unroll
        for (int p=0;p<4;p++){
            int r = p*32 + ar;
            unsigned da = (unsigned)__cvta_generic_to_shared(&dA[r*SA_STRIDE + ac4]);
            CP_ASYNC16(da, Abase + (size_t)r*512 + k0 + ac4);
        }
#pragma unroll
        for (int p=0;p<4;p++){
            int r = p*8 + br;
            unsigned db = (unsigned)__cvta_generic_to_shared(&dB[r*SB_STRIDE + bc4]);
            CP_ASYNC16(db, Bbase + (size_t)(k0+r)*Nn + bc4);
        }
    };

    issue(0, 0); CP_COMMIT;

    int buf = 0;
    for (int kk=0; kk<16; kk++){
        if (kk<15){ issue((kk+1)*32, buf^1); CP_COMMIT; CP_WAIT(1); }
        else      { CP_WAIT(0); }
        __syncthreads();
        unsigned* cA = sA + buf*SA_BUF;
        unsigned* cB = sB + buf*SB_BUF;
#pragma unroll
        for (int ks=0;ks<4;ks++){
            int k8 = ks*8;
            unsigned af[4][4], bf[4][2];
#pragma unroll
            for (int mi=0;mi<4;mi++){
                int rb = wm*64 + mi*16;
                af[mi][0]=cA[(rb+g  )*SA_STRIDE + k8+t4  ];
                af[mi][1]=cA[(rb+g+8)*SA_STRIDE + k8+t4  ];
                af[mi][2]=cA[(rb+g  )*SA_STRIDE + k8+t4+4];
                af[mi][3]=cA[(rb+g+8)*SA_STRIDE + k8+t4+4];
            }
#pragma unroll
            for (int ni=0;ni<4;ni++){
                int cb = wn*32 + ni*8;
                bf[ni][0]=cB[(k8+t4  )*SB_STRIDE + cb+g];
                bf[ni][1]=cB[(k8+t4+4)*SB_STRIDE + cb+g];
            }
#pragma unroll
            for (int mi=0;mi<4;mi++)
#pragma unroll
              for (int ni=0;ni<4;ni++){
                asm volatile(
                  "mma.sync.aligned.m16n8k8.row.col.f32.tf32.tf32.f32 "
                  "{%0,%1,%2,%3}, {%4,%5,%6,%7}, {%8,%9}, {%0,%1,%2,%3};"
                  : "+f"(acc[mi][ni][0]), "+f"(acc[mi][ni][1]),
                    "+f"(acc[mi][ni][2]), "+f"(acc[mi][ni][3])
                  : "r"(af[mi][0]), "r"(af[mi][1]), "r"(af[mi][2]), "r"(af[mi][3]),
                    "r"(bf[ni][0]), "r"(bf[ni][1]));
              }
        }
        __syncthreads();
        buf ^= 1;
    }
    // epilogue
#pragma unroll
    for (int mi=0;mi<4;mi++){
        int r0 = by*128 + wm*64 + mi*16 + g;
#pragma unroll
        for (int ni=0;ni<4;ni++){
            int c0 = bx*128 + wn*32 + ni*8 + 2*t4;
#pragma unroll
            for (int half=0; half<2; half++){
                int r = r0 + half*8;
                float x0 = acc[mi][ni][half*2+0];
                float x1 = acc[mi][ni][half*2+1];
                if (EPI){
                    x0 += bias[c0];  x1 += bias[c0+1];
                    x0  = 0.5f*x0*(1.0f+erff(x0*0.70710678118654752440f));
                    x1  = 0.5f*x1*(1.0f+erff(x1*0.70710678118654752440f));
                    x0 += resid[(size_t)r*Nn + c0];
                    x1 += resid[(size_t)r*Nn + c0+1];
                }
                float2 v2 = make_float2(x0,x1);
                *(float2*)&C[(size_t)r*Nn + c0] = v2;
            }
        }
    }
}

// ---------------- Ball query ----------------
__global__ void ballq_kernel(const float* __restrict__ xyz){
    int gw   = (blockIdx.x*blockDim.x + threadIdx.x)>>5;
    int lane = threadIdx.x & 31;
    int p  =  gw & (NP-1);
    int j  = (gw>>10)&3;
    int bb = (gw>>12)&1;
    int i  =  gw>>13;
    const float* qp = xyz + (size_t)((bb*LQ+i)*NP + p)*3;
    float qx=qp[0], qy=qp[1], qz=qp[2];
    const float* ref = xyz + (size_t)((bb*LQ+j)*NP)*3;
    int cnt=0; int out[NS];
    for (int c=0;c<NP;c+=32){
        const float* rp = ref + (c+lane)*3;
        float dx=rp[0]-qx, dy=rp[1]-qy, dz=rp[2]-qz;
        unsigned mask = __ballot_sync(0xffffffffu, dx*dx+dy*dy+dz*dz < RAD2);
        while (mask && cnt<NS){ int bp=__ffs(mask)-1; out[cnt++]=c+bp; mask&=mask-1; }
        if (cnt>=NS) break;
    }
    int fill = (cnt>0)?out[0]:0;
    for (int s=cnt;s<NS;s++) out[s]=fill;
    if (lane<NS) g_idx[(size_t)gw*NS + lane] = out[lane];
}

// ---------------- Fused attention: coalesced K gather (warp = 4 keys) ----------------
__global__ void attn_kernel(const float* __restrict__ xyz,
                            const float* __restrict__ ws){
    __shared__ float sq[512];
    __shared__ float slog[NHEADS][LK];
    __shared__ float sdisp[LK][3];
    __shared__ int   srow[LK];

    int tid = threadIdx.x;                  // 256
    int p  =  blockIdx.x & (NP-1);
    int bb = (blockIdx.x>>10)&1;
    int i  =  blockIdx.x>>11;
    int rowq = (bb*LQ+i)*NP+p;
    const float* qrow = g_qkv + (size_t)rowq*1536;
    float2 q2 = *(const float2*)(qrow + tid*2);
    sq[tid*2]=q2.x; sq[tid*2+1]=q2.y;
    if (tid<LK){
        int j = tid>>3, s = tid&7;
        int gi   = g_idx[((size_t)((i*BQ+bb)*LQ + j)*NP + p)*NS + s];
        int rowk = (bb*LQ+j)*NP + gi;
        srow[tid]=rowk;
        sdisp[tid][0] = xyz[(size_t)rowk*3+0]-xyz[(size_t)rowq*3+0];
        sdisp[tid][1] = xyz[(size_t)rowk*3+1]-xyz[(size_t)rowq*3+1];
        sdisp[tid][2] = xyz[(size_t)rowk*3+2]-xyz[(size_t)rowq*3+2];
    }
    __syncthreads();

    int w = tid>>5, lane = tid&31;
    int hsub = lane>>4;                     // 0 or 1: which head within a c-slab
    // --- logits: warp w handles keys w*4..w*4+3, lanes span dim (coalesced) ---
#pragma unroll
    for (int jj=0;jj<4;jj++){
        int j = w*4+jj;
        const float* kp = g_qkv + (size_t)srow[j]*1536 + 512 + lane*4;
        float part[4];
#pragma unroll
        for (int c=0;c<4;c++){
            float4 kk = *(const float4*)(kp + c*128);
            const float* qv = &sq[c*128 + lane*4];
            part[c] = kk.x*qv[0]+kk.y*qv[1]+kk.z*qv[2]+kk.w*qv[3];
        }
#pragma unroll
        for (int o=8;o>0;o>>=1){
#pragma unroll
            for (int c=0;c<4;c++) part[c] += __shfl_xor_sync(0xffffffffu,part[c],o);
        }
        if ((lane&15)==0){
#pragma unroll
            for (int c=0;c<4;c++) slog[2*c+hsub][j] = part[c]*0.125f;
        }
    }
    __syncthreads();

    // --- softmax: warp = head, lane = key ---
    int h = w;
    float lg = slog[h][lane];
    float mx = lg;
#pragma unroll
    for (int o=16;o>0;o>>=1) mx = fmaxf(mx, __shfl_xor_sync(0xffffffffu,mx,o));
    float e = expf(lg-mx);
    float sm = e;
#pragma unroll
    for (int o=16;o>0;o>>=1) sm += __shfl_xor_sync(0xffffffffu,sm,o);
    float a = e/sm;
    // --- spatial max term ---
    float m0 = a*sdisp[lane][0], m1 = a*sdisp[lane][1], m2 = a*sdisp[lane][2];
#pragma unroll
    for (int o=16;o>0;o>>=1){
        m0 = fmaxf(m0, __shfl_xor_sync(0xffffffffu,m0,o));
        m1 = fmaxf(m1, __shfl_xor_sync(0xffffffffu,m1,o));
        m2 = fmaxf(m2, __shfl_xor_sync(0xffffffffu,m2,o));
    }
    // --- attn @ V (coalesced, attn weights via shfl) ---
    float acc0=0.f, acc1=0.f;
#pragma unroll 4
    for (int jj=0;jj<LK;jj++){
        float aw = __shfl_sync(0xffffffffu, a, jj);
        const float* vp = g_qkv + (size_t)srow[jj]*1536 + 1024 + h*64 + lane*2;
        float2 vv = *(const float2*)vp;
        acc0 = fmaf(aw, vv.x, acc0);
        acc1 = fmaf(aw, vv.y, acc1);
    }
    int d0 = lane*2;
    float sp0 = m0*ws[d0]   + m1*ws[64+d0]   + m2*ws[128+d0];
    float sp1 = m0*ws[d0+1] + m1*ws[64+d0+1] + m2*ws[128+d0+1];
    float* op = g_attnout + (size_t)rowq*INNER + h*64 + d0;
    op[0]=acc0+sp0; op[1]=acc1+sp1;
}

// ---------------- launch ----------------
extern "C" void kernel_launch(void* const* d_in, const int* in_sizes, int n_in,
                              void* d_out, int out_size){
    const float* xyz       = (const float*)d_in[0];
    const float* feature   = (const float*)d_in[1];
    const float* gamma     = (const float*)d_in[2];
    const float* beta      = (const float*)d_in[3];
    const float* w_qkv     = (const float*)d_in[4];
    const float* w_spatial = (const float*)d_in[5];
    const float* w_out     = (const float*)d_in[6];
    const float* b_out     = (const float*)d_in[7];
    float* out = (float*)d_out;

    void *p_normf=nullptr, *p_qkv=nullptr, *p_attnout=nullptr;
    cudaGetSymbolAddress(&p_normf,   g_normf);
    cudaGetSymbolAddress(&p_qkv,     g_qkv);
    cudaGetSymbolAddress(&p_attnout, g_attnout);

    cudaFuncSetAttribute(mma_gemm<false>,
        cudaFuncAttributeMaxDynamicSharedMemorySize, GEMM_SMEM);
    cudaFuncSetAttribute(mma_gemm<true>,
        cudaFuncAttributeMaxDynamicSharedMemorySize, GEMM_SMEM);

    ln_kernel<<<ROWS,128>>>(feature,gamma,beta);

    dim3 g1(1536/128, ROWS/128);
    mma_gemm<false><<<g1,256,GEMM_SMEM>>>((const float*)p_normf, w_qkv,
                                          (float*)p_qkv, 1536, nullptr, nullptr);

    ballq_kernel<<<(LQ*BQ*LQ*NP*32)/256, 256>>>(xyz);

    attn_kernel<<<LQ*BQ*NP, 256>>>(xyz, w_spatial);

    dim3 g2(512/128, ROWS/128);
    mma_gemm<true><<<g2,256,GEMM_SMEM>>>((const float*)p_attnout, w_out,
                                         out, 512, b_out, feature);
}